// round 2
// baseline (speedup 1.0000x reference)
#include <cuda_runtime.h>
#include <cstdint>

#define N_NODES 100000
#define N_EDGES 1600000
#define HC 128            // HEADS * OUT_CH
#define HEADS 4
#define OUT_CH 32
#define EDGE_CH 32

__constant__ float c_neg_slope = 0.2f;

// ---------------- scratch (static device globals; no allocation) ----------------
__device__ float  g_xl[(size_t)N_NODES * HC];   // 51.2 MB projected node features
__device__ float  g_al[N_NODES * HEADS];        // alpha_l per node/head
__device__ float  g_ar[N_NODES * HEADS];        // alpha_r per node/head
__device__ float  g_we[HC];                     // folded We^T * att_e  [H][32]
__device__ float4 g_alpha[N_EDGES];             // per-edge logits (post leaky-relu), 4 heads
__device__ int4   g_amax[N_NODES];              // encoded float max per node/head
__device__ float4 g_denom[N_NODES];             // softmax denominators

// monotone float<->int encoding for atomicMax on floats
__device__ __forceinline__ int enc_f(float f) {
    int i = __float_as_int(f);
    return (i >= 0) ? i : (i ^ 0x7fffffff);
}
__device__ __forceinline__ float dec_f(int i) {
    return (i >= 0) ? __int_as_float(i) : __int_as_float(i ^ 0x7fffffff);
}

// vectorized 16B global reduction (sm_90+): 4x fewer red ops than scalar atomicAdd
__device__ __forceinline__ void red_add_v4(float4* p, float4 v) {
    asm volatile("red.global.add.v4.f32 [%0], {%1, %2, %3, %4};"
                 :: "l"(p), "f"(v.x), "f"(v.y), "f"(v.z), "f"(v.w)
                 : "memory");
}

// ---------------- kernel 1: init out=bias, amax=-inf(enc), denom=0 ----------------
__global__ void k_init(const float* __restrict__ bias, float* __restrict__ out) {
    int idx = blockIdx.x * blockDim.x + threadIdx.x;
    if (idx < N_NODES * HC) out[idx] = bias[idx & (HC - 1)];
    if (idx < N_NODES * HEADS) {
        ((int*)g_amax)[idx]    = (int)0x80000000;  // below any encoded float
        ((float*)g_denom)[idx] = 0.0f;
    }
}

// ---------------- kernel 2: fold We with att_e  ->  g_we[h*32+k] ----------------
__global__ void k_wepre(const float* __restrict__ We, const float* __restrict__ att_e) {
    int t = threadIdx.x;           // 0..127  = h*32 + k
    int h = t >> 5, k = t & 31;
    float s = 0.0f;
#pragma unroll
    for (int c = 0; c < OUT_CH; c++)
        s += We[(h * OUT_CH + c) * EDGE_CH + k] * att_e[h * OUT_CH + c];
    g_we[t] = s;
}

// ---------------- kernel 3: xl = x @ Wl^T, plus alpha_l / alpha_r ----------------
// block = 128 threads (thread j owns output column j; warp w == head w).
// 4 nodes per iteration, x tile staged in smem, Wl rows stream through L1.
__global__ void k_gemm(const float* __restrict__ x, const float* __restrict__ Wl,
                       const float* __restrict__ att_l, const float* __restrict__ att_r) {
    __shared__ float xs[4][HC];
    const int j    = threadIdx.x;       // 0..127 output column
    const int lane = j & 31;
    const int w    = j >> 5;            // head index
    const float al_w = att_l[j];
    const float ar_w = att_r[j];
    const float4* __restrict__ Wrow = (const float4*)(Wl + (size_t)j * HC); // 32 float4

    for (int base = blockIdx.x * 4; base < N_NODES; base += gridDim.x * 4) {
        __syncthreads();  // previous compute done reading xs
        {   // cooperative load of 4 x-rows (128 float4 across 128 threads)
            int node = j >> 5, off = j & 31;
            ((float4*)xs)[j] = ((const float4*)(x + (size_t)(base + node) * HC))[off];
        }
        __syncthreads();

        float a0 = 0.f, a1 = 0.f, a2 = 0.f, a3 = 0.f;
#pragma unroll 8
        for (int k4 = 0; k4 < HC / 4; k4++) {
            float4 wv = Wrow[k4];
            float4 x0 = ((const float4*)xs[0])[k4];
            float4 x1 = ((const float4*)xs[1])[k4];
            float4 x2 = ((const float4*)xs[2])[k4];
            float4 x3 = ((const float4*)xs[3])[k4];
            a0 += wv.x * x0.x + wv.y * x0.y + wv.z * x0.z + wv.w * x0.w;
            a1 += wv.x * x1.x + wv.y * x1.y + wv.z * x1.z + wv.w * x1.w;
            a2 += wv.x * x2.x + wv.y * x2.y + wv.z * x2.z + wv.w * x2.w;
            a3 += wv.x * x3.x + wv.y * x3.y + wv.z * x3.z + wv.w * x3.w;
        }
        float accs[4] = {a0, a1, a2, a3};
#pragma unroll
        for (int i = 0; i < 4; i++) {
            g_xl[(size_t)(base + i) * HC + j] = accs[i];
            float pl = accs[i] * al_w;
            float pr = accs[i] * ar_w;
#pragma unroll
            for (int off = 16; off; off >>= 1) {
                pl += __shfl_xor_sync(0xffffffffu, pl, off);
                pr += __shfl_xor_sync(0xffffffffu, pr, off);
            }
            if (lane == 0) {
                g_al[(base + i) * HEADS + w] = pl;
                g_ar[(base + i) * HEADS + w] = pr;
            }
        }
    }
}

// ---------------- kernel 4: per-edge logits + leaky-relu + segment max ----------------
// 8 lanes per edge: coalesced 128B edge_attr row, shfl-reduce 4 head dots.
__global__ void k_edge_logits(const float* __restrict__ edge_attr, const int* __restrict__ ei) {
    __shared__ float we_s[HC];
    if (threadIdx.x < HC) we_s[threadIdx.x] = g_we[threadIdx.x];
    __syncthreads();

    const int sub = threadIdx.x & 7;       // lane within edge-group
    const int epb = blockDim.x >> 3;       // edges per block per iter
    for (int e = blockIdx.x * epb + (threadIdx.x >> 3); e < N_EDGES; e += gridDim.x * epb) {
        float4 ea = ((const float4*)edge_attr)[e * 8 + sub];
        const float* w0 = we_s + 0 * 32 + sub * 4;
        const float* w1 = we_s + 1 * 32 + sub * 4;
        const float* w2 = we_s + 2 * 32 + sub * 4;
        const float* w3 = we_s + 3 * 32 + sub * 4;
        float p0 = ea.x * w0[0] + ea.y * w0[1] + ea.z * w0[2] + ea.w * w0[3];
        float p1 = ea.x * w1[0] + ea.y * w1[1] + ea.z * w1[2] + ea.w * w1[3];
        float p2 = ea.x * w2[0] + ea.y * w2[1] + ea.z * w2[2] + ea.w * w2[3];
        float p3 = ea.x * w3[0] + ea.y * w3[1] + ea.z * w3[2] + ea.w * w3[3];
#pragma unroll
        for (int off = 4; off; off >>= 1) {
            p0 += __shfl_down_sync(0xffffffffu, p0, off, 8);
            p1 += __shfl_down_sync(0xffffffffu, p1, off, 8);
            p2 += __shfl_down_sync(0xffffffffu, p2, off, 8);
            p3 += __shfl_down_sync(0xffffffffu, p3, off, 8);
        }
        if (sub == 0) {
            int src = ei[e];
            int dst = ei[N_EDGES + e];
            const float* alv = g_al + (size_t)src * HEADS;
            const float* arv = g_ar + (size_t)dst * HEADS;
            float a0 = alv[0] + arv[0] + p0;
            float a1 = alv[1] + arv[1] + p1;
            float a2 = alv[2] + arv[2] + p2;
            float a3 = alv[3] + arv[3] + p3;
            a0 = (a0 > 0.f) ? a0 : c_neg_slope * a0;
            a1 = (a1 > 0.f) ? a1 : c_neg_slope * a1;
            a2 = (a2 > 0.f) ? a2 : c_neg_slope * a2;
            a3 = (a3 > 0.f) ? a3 : c_neg_slope * a3;
            g_alpha[e] = make_float4(a0, a1, a2, a3);
            int* am = (int*)(g_amax + dst);
            atomicMax(am + 0, enc_f(a0));
            atomicMax(am + 1, enc_f(a1));
            atomicMax(am + 2, enc_f(a2));
            atomicMax(am + 3, enc_f(a3));
        }
    }
}

// ---------------- kernel 5: softmax denominators ----------------
__global__ void k_denom(const int* __restrict__ ei) {
    int e = blockIdx.x * blockDim.x + threadIdx.x;
    if (e >= N_EDGES) return;
    int dst = ei[N_EDGES + e];
    float4 a  = g_alpha[e];
    int4   mi = g_amax[dst];
    float4 ex = make_float4(expf(a.x - dec_f(mi.x)),
                            expf(a.y - dec_f(mi.y)),
                            expf(a.z - dec_f(mi.z)),
                            expf(a.w - dec_f(mi.w)));
    red_add_v4(&g_denom[dst], ex);
}

// ---------------- kernel 6: normalized weighted scatter-add ----------------
// one warp per edge: lane j gathers float4 of xl[src] (512B coalesced), scales by
// its head's alpha_n, red.v4 into out[dst]. Heavy pass — L2-bandwidth bound.
__global__ void k_agg(const int* __restrict__ ei, float* __restrict__ out) {
    const int lane = threadIdx.x & 31;
    const int h    = lane >> 3;                 // head = lane/8 (4 float4 per head)
    const int wpb  = blockDim.x >> 5;
    const int total_warps = gridDim.x * wpb;
    for (int e = blockIdx.x * wpb + ((int)threadIdx.x >> 5); e < N_EDGES; e += total_warps) {
        int src = ei[e];
        int dst = ei[N_EDGES + e];
        float a  = ((const float*)g_alpha)[(size_t)e * 4 + h];
        int   mi = ((const int*)g_amax)[(size_t)dst * 4 + h];
        float d  = ((const float*)g_denom)[(size_t)dst * 4 + h];
        float an = expf(a - dec_f(mi)) / (d + 1e-16f);
        float4 v = ((const float4*)g_xl)[(size_t)src * 32 + lane];
        v.x *= an; v.y *= an; v.z *= an; v.w *= an;
        red_add_v4((float4*)out + (size_t)dst * 32 + lane, v);
    }
}

// ---------------- launch ----------------
extern "C" void kernel_launch(void* const* d_in, const int* in_sizes, int n_in,
                              void* d_out, int out_size) {
    const float* x         = (const float*)d_in[0];
    const float* edge_attr = (const float*)d_in[1];
    const float* Wl        = (const float*)d_in[2];
    const float* We        = (const float*)d_in[3];
    const float* att_l     = (const float*)d_in[4];
    const float* att_r     = (const float*)d_in[5];
    const float* att_e     = (const float*)d_in[6];
    const float* bias      = (const float*)d_in[7];
    const int*   ei        = (const int*)d_in[8];
    float* out = (float*)d_out;

    k_init<<<(N_NODES * HC + 255) / 256, 256>>>(bias, out);
    k_wepre<<<1, 128>>>(We, att_e);
    k_gemm<<<2368, 128>>>(x, Wl, att_l, att_r);
    k_edge_logits<<<1184, 256>>>(edge_attr, ei);
    k_denom<<<(N_EDGES + 255) / 256, 256>>>(ei);
    k_agg<<<1184, 256>>>(ei, out);
}

// round 3
// speedup vs baseline: 1.2689x; 1.2689x over previous
#include <cuda_runtime.h>
#include <cstdint>

#define N_NODES 100000
#define N_EDGES 1600000
#define HC 128            // HEADS * OUT_CH
#define HEADS 4
#define OUT_CH 32
#define EDGE_CH 32
#define SCAN_BLK 1024
#define SCAN_NB ((N_NODES + SCAN_BLK - 1) / SCAN_BLK)   // 98

__constant__ float c_neg_slope = 0.2f;

// ---------------- scratch (static device globals; no allocation) ----------------
__device__ float  g_xl[(size_t)N_NODES * HC];   // 51.2 MB projected node features
__device__ float  g_al[N_NODES * HEADS];        // alpha_l per node/head
__device__ float  g_ar[N_NODES * HEADS];        // alpha_r per node/head
__device__ float  g_we[HC];                     // folded We^T * att_e  [H][32]
__device__ float4 g_ex[N_EDGES];                // per-edge exp(logit), 4 heads
__device__ float4 g_denom[N_NODES];             // softmax denominators
__device__ int    g_hist[N_NODES];              // in-degree histogram
__device__ int    g_offs[N_NODES];              // CSR start offsets (exclusive scan)
__device__ int    g_cursor[N_NODES];            // scatter cursors (end offsets after)
__device__ int    g_bsum[SCAN_NB];              // scan block sums
__device__ int    g_csr_src[N_EDGES];           // dst-sorted source node ids
__device__ float4 g_csr_an[N_EDGES];            // dst-sorted normalized alphas

// vectorized 16B global reduction (sm_90+)
__device__ __forceinline__ void red_add_v4(float4* p, float4 v) {
    asm volatile("red.global.add.v4.f32 [%0], {%1, %2, %3, %4};"
                 :: "l"(p), "f"(v.x), "f"(v.y), "f"(v.z), "f"(v.w)
                 : "memory");
}

// ---------------- kernel 0: zero hist + denom ----------------
__global__ void k_zero() {
    int idx = blockIdx.x * blockDim.x + threadIdx.x;
    if (idx < N_NODES * HEADS) ((float*)g_denom)[idx] = 0.0f;
    if (idx < N_NODES) g_hist[idx] = 0;
}

// ---------------- kernel: fold We with att_e  ->  g_we[h*32+k] ----------------
__global__ void k_wepre(const float* __restrict__ We, const float* __restrict__ att_e) {
    int t = threadIdx.x;           // 0..127  = h*32 + k
    int h = t >> 5, k = t & 31;
    float s = 0.0f;
#pragma unroll
    for (int c = 0; c < OUT_CH; c++)
        s += We[(h * OUT_CH + c) * EDGE_CH + k] * att_e[h * OUT_CH + c];
    g_we[t] = s;
}

// ---------------- kernel: xl = x @ Wl^T, plus alpha_l / alpha_r ----------------
__global__ void k_gemm(const float* __restrict__ x, const float* __restrict__ Wl,
                       const float* __restrict__ att_l, const float* __restrict__ att_r) {
    __shared__ float xs[4][HC];
    const int j    = threadIdx.x;       // 0..127 output column
    const int lane = j & 31;
    const int w    = j >> 5;            // head index
    const float al_w = att_l[j];
    const float ar_w = att_r[j];
    const float4* __restrict__ Wrow = (const float4*)(Wl + (size_t)j * HC); // 32 float4

    for (int base = blockIdx.x * 4; base < N_NODES; base += gridDim.x * 4) {
        __syncthreads();
        {
            int node = j >> 5, off = j & 31;
            ((float4*)xs)[j] = ((const float4*)(x + (size_t)(base + node) * HC))[off];
        }
        __syncthreads();

        float a0 = 0.f, a1 = 0.f, a2 = 0.f, a3 = 0.f;
#pragma unroll 8
        for (int k4 = 0; k4 < HC / 4; k4++) {
            float4 wv = Wrow[k4];
            float4 x0 = ((const float4*)xs[0])[k4];
            float4 x1 = ((const float4*)xs[1])[k4];
            float4 x2 = ((const float4*)xs[2])[k4];
            float4 x3 = ((const float4*)xs[3])[k4];
            a0 += wv.x * x0.x + wv.y * x0.y + wv.z * x0.z + wv.w * x0.w;
            a1 += wv.x * x1.x + wv.y * x1.y + wv.z * x1.z + wv.w * x1.w;
            a2 += wv.x * x2.x + wv.y * x2.y + wv.z * x2.z + wv.w * x2.w;
            a3 += wv.x * x3.x + wv.y * x3.y + wv.z * x3.z + wv.w * x3.w;
        }
        float accs[4] = {a0, a1, a2, a3};
#pragma unroll
        for (int i = 0; i < 4; i++) {
            g_xl[(size_t)(base + i) * HC + j] = accs[i];
            float pl = accs[i] * al_w;
            float pr = accs[i] * ar_w;
#pragma unroll
            for (int off = 16; off; off >>= 1) {
                pl += __shfl_xor_sync(0xffffffffu, pl, off);
                pr += __shfl_xor_sync(0xffffffffu, pr, off);
            }
            if (lane == 0) {
                g_al[(base + i) * HEADS + w] = pl;
                g_ar[(base + i) * HEADS + w] = pr;
            }
        }
    }
}

// ---------------- fused: logits + leaky-relu + exp + denom + degree hist ----------------
// thread per edge; shift-free softmax (logit magnitudes are O(10), safe in fp32).
__global__ void k_logits(const float* __restrict__ edge_attr, const int* __restrict__ ei) {
    __shared__ float we_s[HC];
    if (threadIdx.x < HC) we_s[threadIdx.x] = g_we[threadIdx.x];
    __syncthreads();

    int e = blockIdx.x * blockDim.x + threadIdx.x;
    if (e >= N_EDGES) return;

    const float4* __restrict__ row = (const float4*)(edge_attr + (size_t)e * EDGE_CH);
    float p0 = 0.f, p1 = 0.f, p2 = 0.f, p3 = 0.f;
#pragma unroll
    for (int i = 0; i < 8; i++) {
        float4 v = row[i];
        int b = i * 4;
        p0 += v.x * we_s[0 * 32 + b] + v.y * we_s[0 * 32 + b + 1] + v.z * we_s[0 * 32 + b + 2] + v.w * we_s[0 * 32 + b + 3];
        p1 += v.x * we_s[1 * 32 + b] + v.y * we_s[1 * 32 + b + 1] + v.z * we_s[1 * 32 + b + 2] + v.w * we_s[1 * 32 + b + 3];
        p2 += v.x * we_s[2 * 32 + b] + v.y * we_s[2 * 32 + b + 1] + v.z * we_s[2 * 32 + b + 2] + v.w * we_s[2 * 32 + b + 3];
        p3 += v.x * we_s[3 * 32 + b] + v.y * we_s[3 * 32 + b + 1] + v.z * we_s[3 * 32 + b + 2] + v.w * we_s[3 * 32 + b + 3];
    }
    int src = ei[e];
    int dst = ei[N_EDGES + e];
    float4 al = ((const float4*)g_al)[src];
    float4 ar = ((const float4*)g_ar)[dst];
    float a0 = al.x + ar.x + p0;
    float a1 = al.y + ar.y + p1;
    float a2 = al.z + ar.z + p2;
    float a3 = al.w + ar.w + p3;
    a0 = (a0 > 0.f) ? a0 : c_neg_slope * a0;
    a1 = (a1 > 0.f) ? a1 : c_neg_slope * a1;
    a2 = (a2 > 0.f) ? a2 : c_neg_slope * a2;
    a3 = (a3 > 0.f) ? a3 : c_neg_slope * a3;
    float4 ex = make_float4(__expf(a0), __expf(a1), __expf(a2), __expf(a3));
    g_ex[e] = ex;
    red_add_v4(&g_denom[dst], ex);
    atomicAdd(&g_hist[dst], 1);
}

// ---------------- scan kernels: exclusive prefix over g_hist -> g_offs ----------------
__global__ void k_scan1() {
    __shared__ int wsum[32];
    int i = blockIdx.x * SCAN_BLK + threadIdx.x;
    int lane = threadIdx.x & 31, wid = threadIdx.x >> 5;
    int v = (i < N_NODES) ? g_hist[i] : 0;
    int inc = v;
#pragma unroll
    for (int off = 1; off < 32; off <<= 1) {
        int t = __shfl_up_sync(0xffffffffu, inc, off);
        if (lane >= off) inc += t;
    }
    if (lane == 31) wsum[wid] = inc;
    __syncthreads();
    if (wid == 0) {
        int s = wsum[lane];
#pragma unroll
        for (int off = 1; off < 32; off <<= 1) {
            int t = __shfl_up_sync(0xffffffffu, s, off);
            if (lane >= off) s += t;
        }
        wsum[lane] = s;
    }
    __syncthreads();
    int base = (wid > 0) ? wsum[wid - 1] : 0;
    if (i < N_NODES) g_offs[i] = base + inc - v;     // exclusive within block
    if (threadIdx.x == SCAN_BLK - 1) g_bsum[blockIdx.x] = base + inc;  // block total
}

__global__ void k_scan2() {   // single block, scan SCAN_NB (=98) block totals, exclusive
    __shared__ int wsum[4];
    int lane = threadIdx.x & 31, wid = threadIdx.x >> 5;
    int v = (threadIdx.x < SCAN_NB) ? g_bsum[threadIdx.x] : 0;
    int inc = v;
#pragma unroll
    for (int off = 1; off < 32; off <<= 1) {
        int t = __shfl_up_sync(0xffffffffu, inc, off);
        if (lane >= off) inc += t;
    }
    if (lane == 31) wsum[wid] = inc;
    __syncthreads();
    int base = 0;
    for (int w = 0; w < wid; w++) base += wsum[w];
    if (threadIdx.x < SCAN_NB) g_bsum[threadIdx.x] = base + inc - v;
}

__global__ void k_scan3() {   // apply block offsets; init cursor = offs
    int i = blockIdx.x * SCAN_BLK + threadIdx.x;
    if (i < N_NODES) {
        int o = g_offs[i] + g_bsum[blockIdx.x];
        g_offs[i]   = o;
        g_cursor[i] = o;
    }
}

// ---------------- scatter into CSR with pre-normalized alpha ----------------
__global__ void k_scatter(const int* __restrict__ ei) {
    int e = blockIdx.x * blockDim.x + threadIdx.x;
    if (e >= N_EDGES) return;
    int src = ei[e];
    int dst = ei[N_EDGES + e];
    float4 ex = g_ex[e];
    float4 dn = g_denom[dst];
    float4 an = make_float4(ex.x / (dn.x + 1e-16f), ex.y / (dn.y + 1e-16f),
                            ex.z / (dn.z + 1e-16f), ex.w / (dn.w + 1e-16f));
    int pos = atomicAdd(&g_cursor[dst], 1);
    g_csr_src[pos] = src;
    g_csr_an[pos]  = an;
}

// ---------------- gather aggregation: one warp per dst node, no output atomics ----------------
__global__ void k_agg(const float* __restrict__ bias, float* __restrict__ out) {
    const int lane = threadIdx.x & 31;
    const int h    = lane >> 3;                 // head owning this lane's float4
    int node = blockIdx.x * (blockDim.x >> 5) + (threadIdx.x >> 5);
    if (node >= N_NODES) return;

    int beg = g_offs[node];
    int end = g_cursor[node];                   // after scatter: start + degree
    float4 acc = make_float4(0.f, 0.f, 0.f, 0.f);

    int pos = beg;
    for (; pos + 1 < end; pos += 2) {
        int s0 = g_csr_src[pos];
        int s1 = g_csr_src[pos + 1];
        float a0 = ((const float*)g_csr_an)[(size_t)pos * 4 + h];
        float a1 = ((const float*)g_csr_an)[(size_t)(pos + 1) * 4 + h];
        float4 v0 = ((const float4*)g_xl)[(size_t)s0 * 32 + lane];
        float4 v1 = ((const float4*)g_xl)[(size_t)s1 * 32 + lane];
        acc.x += a0 * v0.x + a1 * v1.x;
        acc.y += a0 * v0.y + a1 * v1.y;
        acc.z += a0 * v0.z + a1 * v1.z;
        acc.w += a0 * v0.w + a1 * v1.w;
    }
    if (pos < end) {
        int s0 = g_csr_src[pos];
        float a0 = ((const float*)g_csr_an)[(size_t)pos * 4 + h];
        float4 v0 = ((const float4*)g_xl)[(size_t)s0 * 32 + lane];
        acc.x += a0 * v0.x; acc.y += a0 * v0.y; acc.z += a0 * v0.z; acc.w += a0 * v0.w;
    }
    float4 b = ((const float4*)bias)[lane];
    acc.x += b.x; acc.y += b.y; acc.z += b.z; acc.w += b.w;
    ((float4*)out)[(size_t)node * 32 + lane] = acc;
}

// ---------------- launch ----------------
extern "C" void kernel_launch(void* const* d_in, const int* in_sizes, int n_in,
                              void* d_out, int out_size) {
    const float* x         = (const float*)d_in[0];
    const float* edge_attr = (const float*)d_in[1];
    const float* Wl        = (const float*)d_in[2];
    const float* We        = (const float*)d_in[3];
    const float* att_l     = (const float*)d_in[4];
    const float* att_r     = (const float*)d_in[5];
    const float* att_e     = (const float*)d_in[6];
    const float* bias      = (const float*)d_in[7];
    const int*   ei        = (const int*)d_in[8];
    float* out = (float*)d_out;

    k_zero<<<(N_NODES * HEADS + 255) / 256, 256>>>();
    k_wepre<<<1, 128>>>(We, att_e);
    k_gemm<<<2368, 128>>>(x, Wl, att_l, att_r);
    k_logits<<<(N_EDGES + 255) / 256, 256>>>(edge_attr, ei);
    k_scan1<<<SCAN_NB, SCAN_BLK>>>();
    k_scan2<<<1, 128>>>();
    k_scan3<<<SCAN_NB, SCAN_BLK>>>();
    k_scatter<<<(N_EDGES + 255) / 256, 256>>>(ei);
    k_agg<<<(N_NODES * 32 + 255) / 256, 256>>>(bias, out);
}

// round 4
// speedup vs baseline: 1.8454x; 1.4544x over previous
#include <cuda_runtime.h>
#include <cstdint>

#define N_NODES 100000
#define N_EDGES 1600000
#define HC 128            // HEADS * OUT_CH
#define HEADS 4
#define OUT_CH 32
#define EDGE_CH 32
#define SCAN_BLK 1024
#define SCAN_NB ((N_NODES + SCAN_BLK - 1) / SCAN_BLK)   // 98

__constant__ float c_neg_slope = 0.2f;

// ---------------- scratch (static device globals; no allocation) ----------------
__device__ float  g_xl[(size_t)N_NODES * HC];   // 51.2 MB projected node features
__device__ float  g_al[N_NODES * HEADS];        // alpha_l per node/head
__device__ float  g_ar[N_NODES * HEADS];        // alpha_r per node/head
__device__ float  g_we[HC];                     // folded We^T * att_e  [H][32]
__device__ float4 g_denom[N_NODES];             // softmax denominators (sum of ex)
__device__ int    g_hist[N_NODES];              // in-degree histogram
__device__ int    g_offs[N_NODES];              // CSR start offsets (exclusive scan)
__device__ int    g_cursor[N_NODES];            // scatter cursors
__device__ int    g_bsum[SCAN_NB];              // scan block sums
__device__ int    g_csr_src[N_EDGES];           // dst-sorted source node ids
__device__ float4 g_csr_ex[N_EDGES];            // dst-sorted UNnormalized exp(logit)

// vectorized 16B global reduction (sm_90+)
__device__ __forceinline__ void red_add_v4(float4* p, float4 v) {
    asm volatile("red.global.add.v4.f32 [%0], {%1, %2, %3, %4};"
                 :: "l"(p), "f"(v.x), "f"(v.y), "f"(v.z), "f"(v.w)
                 : "memory");
}

// ---------------- zero hist + denom ----------------
__global__ void k_zero() {
    int idx = blockIdx.x * blockDim.x + threadIdx.x;
    if (idx < N_NODES * HEADS) ((float*)g_denom)[idx] = 0.0f;
    if (idx < N_NODES) g_hist[idx] = 0;
}

// ---------------- fold We with att_e  ->  g_we[h*32+k] ----------------
__global__ void k_wepre(const float* __restrict__ We, const float* __restrict__ att_e) {
    int t = threadIdx.x;           // 0..127  = h*32 + k
    int h = t >> 5, k = t & 31;
    float s = 0.0f;
#pragma unroll
    for (int c = 0; c < OUT_CH; c++)
        s += We[(h * OUT_CH + c) * EDGE_CH + k] * att_e[h * OUT_CH + c];
    g_we[t] = s;
}

// ---------------- in-degree histogram (dst only, int4 vectorized) ----------------
__global__ void k_hist(const int* __restrict__ ei) {
    int i = blockIdx.x * blockDim.x + threadIdx.x;   // quad index
    if (i * 4 >= N_EDGES) return;
    int4 d = ((const int4*)(ei + N_EDGES))[i];
    atomicAdd(&g_hist[d.x], 1);
    atomicAdd(&g_hist[d.y], 1);
    atomicAdd(&g_hist[d.z], 1);
    atomicAdd(&g_hist[d.w], 1);
}

// ---------------- xl = x @ Wl^T, plus alpha_l / alpha_r (8-node tiles) ----------------
__global__ void k_gemm(const float* __restrict__ x, const float* __restrict__ Wl,
                       const float* __restrict__ att_l, const float* __restrict__ att_r) {
    __shared__ float xs[8][HC];
    const int j    = threadIdx.x;       // 0..127 output column
    const int lane = j & 31;
    const int w    = j >> 5;            // head index
    const float al_w = att_l[j];
    const float ar_w = att_r[j];
    const float4* __restrict__ Wrow = (const float4*)(Wl + (size_t)j * HC); // 32 float4

    for (int base = blockIdx.x * 8; base < N_NODES; base += gridDim.x * 8) {
        __syncthreads();
        {   // cooperative load of 8 x-rows: 256 float4 / 128 threads = 2 each
            const float4* src = (const float4*)(x + (size_t)base * HC);
            ((float4*)xs)[j]       = src[j];
            ((float4*)xs)[j + 128] = src[j + 128];
        }
        __syncthreads();

        float acc[8];
#pragma unroll
        for (int i = 0; i < 8; i++) acc[i] = 0.f;
#pragma unroll 4
        for (int k4 = 0; k4 < HC / 4; k4++) {
            float4 wv = Wrow[k4];
#pragma unroll
            for (int i = 0; i < 8; i++) {
                float4 xv = ((const float4*)xs[i])[k4];
                acc[i] += wv.x * xv.x + wv.y * xv.y + wv.z * xv.z + wv.w * xv.w;
            }
        }
#pragma unroll
        for (int i = 0; i < 8; i++) {
            g_xl[(size_t)(base + i) * HC + j] = acc[i];
            float pl = acc[i] * al_w;
            float pr = acc[i] * ar_w;
#pragma unroll
            for (int off = 16; off; off >>= 1) {
                pl += __shfl_xor_sync(0xffffffffu, pl, off);
                pr += __shfl_xor_sync(0xffffffffu, pr, off);
            }
            if (lane == 0) {
                g_al[(base + i) * HEADS + w] = pl;
                g_ar[(base + i) * HEADS + w] = pr;
            }
        }
    }
}

// ---------------- scan kernels: exclusive prefix over g_hist -> g_offs ----------------
__global__ void k_scan1() {
    __shared__ int wsum[32];
    int i = blockIdx.x * SCAN_BLK + threadIdx.x;
    int lane = threadIdx.x & 31, wid = threadIdx.x >> 5;
    int v = (i < N_NODES) ? g_hist[i] : 0;
    int inc = v;
#pragma unroll
    for (int off = 1; off < 32; off <<= 1) {
        int t = __shfl_up_sync(0xffffffffu, inc, off);
        if (lane >= off) inc += t;
    }
    if (lane == 31) wsum[wid] = inc;
    __syncthreads();
    if (wid == 0) {
        int s = wsum[lane];
#pragma unroll
        for (int off = 1; off < 32; off <<= 1) {
            int t = __shfl_up_sync(0xffffffffu, s, off);
            if (lane >= off) s += t;
        }
        wsum[lane] = s;
    }
    __syncthreads();
    int base = (wid > 0) ? wsum[wid - 1] : 0;
    if (i < N_NODES) g_offs[i] = base + inc - v;
    if (threadIdx.x == SCAN_BLK - 1) g_bsum[blockIdx.x] = base + inc;
}

__global__ void k_scan2() {   // single block, scan SCAN_NB (=98) block totals, exclusive
    __shared__ int wsum[4];
    int lane = threadIdx.x & 31, wid = threadIdx.x >> 5;
    int v = (threadIdx.x < SCAN_NB) ? g_bsum[threadIdx.x] : 0;
    int inc = v;
#pragma unroll
    for (int off = 1; off < 32; off <<= 1) {
        int t = __shfl_up_sync(0xffffffffu, inc, off);
        if (lane >= off) inc += t;
    }
    if (lane == 31) wsum[wid] = inc;
    __syncthreads();
    int base = 0;
    for (int w = 0; w < wid; w++) base += wsum[w];
    if (threadIdx.x < SCAN_NB) g_bsum[threadIdx.x] = base + inc - v;
}

__global__ void k_scan3() {   // apply block offsets; init cursor = offs
    int i = blockIdx.x * SCAN_BLK + threadIdx.x;
    if (i < N_NODES) {
        int o = g_offs[i] + g_bsum[blockIdx.x];
        g_offs[i]   = o;
        g_cursor[i] = o;
    }
}

// ---------------- fused: logits + leaky-relu + exp + denom + CSR scatter ----------------
// thread per edge; shift-free softmax; scatter UNnormalized ex into CSR slot.
__global__ void k_logits(const float* __restrict__ edge_attr, const int* __restrict__ ei) {
    __shared__ float we_s[HC];
    if (threadIdx.x < HC) we_s[threadIdx.x] = g_we[threadIdx.x];
    __syncthreads();

    int e = blockIdx.x * blockDim.x + threadIdx.x;
    if (e >= N_EDGES) return;

    const float4* __restrict__ row = (const float4*)(edge_attr + (size_t)e * EDGE_CH);
    const float4* w0 = (const float4*)(we_s);
    const float4* w1 = (const float4*)(we_s + 32);
    const float4* w2 = (const float4*)(we_s + 64);
    const float4* w3 = (const float4*)(we_s + 96);
    float p0 = 0.f, p1 = 0.f, p2 = 0.f, p3 = 0.f;
#pragma unroll
    for (int i = 0; i < 8; i++) {
        float4 v = row[i];
        float4 a0 = w0[i], a1 = w1[i], a2 = w2[i], a3 = w3[i];
        p0 += v.x * a0.x + v.y * a0.y + v.z * a0.z + v.w * a0.w;
        p1 += v.x * a1.x + v.y * a1.y + v.z * a1.z + v.w * a1.w;
        p2 += v.x * a2.x + v.y * a2.y + v.z * a2.z + v.w * a2.w;
        p3 += v.x * a3.x + v.y * a3.y + v.z * a3.z + v.w * a3.w;
    }
    int src = ei[e];
    int dst = ei[N_EDGES + e];
    float4 al = ((const float4*)g_al)[src];
    float4 ar = ((const float4*)g_ar)[dst];
    float a0 = al.x + ar.x + p0;
    float a1 = al.y + ar.y + p1;
    float a2 = al.z + ar.z + p2;
    float a3 = al.w + ar.w + p3;
    a0 = (a0 > 0.f) ? a0 : c_neg_slope * a0;
    a1 = (a1 > 0.f) ? a1 : c_neg_slope * a1;
    a2 = (a2 > 0.f) ? a2 : c_neg_slope * a2;
    a3 = (a3 > 0.f) ? a3 : c_neg_slope * a3;
    float4 ex = make_float4(__expf(a0), __expf(a1), __expf(a2), __expf(a3));
    int pos = atomicAdd(&g_cursor[dst], 1);
    g_csr_src[pos] = src;
    g_csr_ex[pos]  = ex;
    red_add_v4(&g_denom[dst], ex);
}

// ---------------- gather aggregation: one warp per dst node ----------------
// normalize by denom in the epilogue:  out = (sum ex_i * xl[src_i]) / (denom+eps) + bias
__global__ void k_agg(const float* __restrict__ bias, float* __restrict__ out) {
    const int lane = threadIdx.x & 31;
    const int h    = lane >> 3;                 // head owning this lane's float4
    int node = blockIdx.x * (blockDim.x >> 5) + (threadIdx.x >> 5);
    if (node >= N_NODES) return;

    int beg = g_offs[node];
    int end = g_cursor[node];                   // start + degree
    float4 acc = make_float4(0.f, 0.f, 0.f, 0.f);

    int pos = beg;
    for (; pos + 3 < end; pos += 4) {
        int s0 = g_csr_src[pos];
        int s1 = g_csr_src[pos + 1];
        int s2 = g_csr_src[pos + 2];
        int s3 = g_csr_src[pos + 3];
        float a0 = ((const float*)g_csr_ex)[(size_t)pos * 4 + h];
        float a1 = ((const float*)g_csr_ex)[(size_t)(pos + 1) * 4 + h];
        float a2 = ((const float*)g_csr_ex)[(size_t)(pos + 2) * 4 + h];
        float a3 = ((const float*)g_csr_ex)[(size_t)(pos + 3) * 4 + h];
        float4 v0 = ((const float4*)g_xl)[(size_t)s0 * 32 + lane];
        float4 v1 = ((const float4*)g_xl)[(size_t)s1 * 32 + lane];
        float4 v2 = ((const float4*)g_xl)[(size_t)s2 * 32 + lane];
        float4 v3 = ((const float4*)g_xl)[(size_t)s3 * 32 + lane];
        acc.x += a0 * v0.x + a1 * v1.x + a2 * v2.x + a3 * v3.x;
        acc.y += a0 * v0.y + a1 * v1.y + a2 * v2.y + a3 * v3.y;
        acc.z += a0 * v0.z + a1 * v1.z + a2 * v2.z + a3 * v3.z;
        acc.w += a0 * v0.w + a1 * v1.w + a2 * v2.w + a3 * v3.w;
    }
    for (; pos < end; pos++) {
        int s0 = g_csr_src[pos];
        float a0 = ((const float*)g_csr_ex)[(size_t)pos * 4 + h];
        float4 v0 = ((const float4*)g_xl)[(size_t)s0 * 32 + lane];
        acc.x += a0 * v0.x; acc.y += a0 * v0.y; acc.z += a0 * v0.z; acc.w += a0 * v0.w;
    }
    float inv = 1.0f / (((const float*)g_denom)[(size_t)node * 4 + h] + 1e-16f);
    float4 b = ((const float4*)bias)[lane];
    acc.x = acc.x * inv + b.x;
    acc.y = acc.y * inv + b.y;
    acc.z = acc.z * inv + b.z;
    acc.w = acc.w * inv + b.w;
    ((float4*)out)[(size_t)node * 32 + lane] = acc;
}

// ---------------- launch ----------------
extern "C" void kernel_launch(void* const* d_in, const int* in_sizes, int n_in,
                              void* d_out, int out_size) {
    const float* x         = (const float*)d_in[0];
    const float* edge_attr = (const float*)d_in[1];
    const float* Wl        = (const float*)d_in[2];
    const float* We        = (const float*)d_in[3];
    const float* att_l     = (const float*)d_in[4];
    const float* att_r     = (const float*)d_in[5];
    const float* att_e     = (const float*)d_in[6];
    const float* bias      = (const float*)d_in[7];
    const int*   ei        = (const int*)d_in[8];
    float* out = (float*)d_out;

    k_zero<<<(N_NODES * HEADS + 255) / 256, 256>>>();
    k_wepre<<<1, 128>>>(We, att_e);
    k_hist<<<(N_EDGES / 4 + 255) / 256, 256>>>(ei);
    k_scan1<<<SCAN_NB, SCAN_BLK>>>();
    k_scan2<<<1, 128>>>();
    k_scan3<<<SCAN_NB, SCAN_BLK>>>();
    k_gemm<<<2368, 128>>>(x, Wl, att_l, att_r);
    k_logits<<<(N_EDGES + 255) / 256, 256>>>(edge_attr, ei);
    k_agg<<<(N_NODES * 32 + 255) / 256, 256>>>(bias, out);
}